// round 7
// baseline (speedup 1.0000x reference)
#include <cuda_runtime.h>
#include <cstdint>

#define T_MAX 512
#define B_SZ  64
#define IND   300
#define DIM   1024
#define TD    (T_MAX * DIM)
#define NCTA  128
#define HALF_CTAS 64
#define XST   1032               // x row stride in floats (bank-stagger, 16B-aligned)

__device__ unsigned g_bar[2 * T_MAX];
__device__ int      g_len[B_SZ];

union F2U { float2 f; unsigned long long u; };

__device__ __forceinline__ unsigned long long fma2(unsigned long long a,
                                                   unsigned long long b,
                                                   unsigned long long c) {
    unsigned long long d;
    asm("fma.rn.f32x2 %0, %1, %2, %3;" : "=l"(d) : "l"(a), "l"(b), "l"(c));
    return d;
}
__device__ __forceinline__ unsigned long long add2(unsigned long long a,
                                                   unsigned long long b) {
    unsigned long long d;
    asm("add.rn.f32x2 %0, %1, %2;" : "=l"(d) : "l"(a), "l"(b));
    return d;
}

// ---------------------------------------------------------------------------
__global__ void zero_kernel() {
    int i = blockIdx.x * blockDim.x + threadIdx.x;
    if (i < 2 * T_MAX) g_bar[i] = 0u;
    if (i < B_SZ)      g_len[i] = 0;
}

// ---------------------------------------------------------------------------
__global__ void __launch_bounds__(256) prep_kernel(const float* __restrict__ emb) {
    int b  = blockIdx.x & 63;
    int tq = blockIdx.x >> 6;
    int row = threadIdx.x >> 2;
    int l4  = threadIdx.x & 3;
    int t = tq * 64 + row;
    const float* p = emb + ((size_t)t * B_SZ + b) * IND;
    float s = 0.f;
    for (int i = l4; i < IND; i += 4) s += p[i];
    s += __shfl_xor_sync(~0u, s, 1);
    s += __shfl_xor_sync(~0u, s, 2);
    unsigned ball = __ballot_sync(~0u, (l4 == 0) && (s != 0.f));
    if ((threadIdx.x & 31) == 0) atomicAdd(&g_len[b], __popc(ball));
}

// ---------------------------------------------------------------------------
__global__ void tail_kernel(float* __restrict__ out, int out_size) {
    int b = threadIdx.x;
    long long tail = (long long)T_MAX * B_SZ * DIM;
    if (b < B_SZ && (long long)out_size >= tail + B_SZ)
        out[tail + b] = (float)g_len[b];
}

// ---------------------------------------------------------------------------
// ugemm: u[t,b,:] = input_w @ emb[t,b,:] + bias -> out[b,t,:]
// ---------------------------------------------------------------------------
#define KT 32
__global__ void __launch_bounds__(256) ugemm_kernel(const float* __restrict__ emb,
                                                    const float* __restrict__ win,
                                                    const float* __restrict__ bias,
                                                    float* __restrict__ out) {
    __shared__ float As[KT][68];
    __shared__ float Bs[KT][136];

    const int t  = blockIdx.x;
    const int n0 = blockIdx.y * 128;
    const int tid = threadIdx.x;
    const int tx = tid & 15, ty = tid >> 4;
    const float* arow = emb + (size_t)t * B_SZ * IND;

    float acc[4][8];
    #pragma unroll
    for (int i = 0; i < 4; i++)
        #pragma unroll
        for (int j = 0; j < 8; j++) acc[i][j] = 0.f;

    for (int kk = 0; kk < IND; kk += KT) {
        #pragma unroll
        for (int s = 0; s < 2; s++) {
            int idx = tid + s * 256;
            int row = idx >> 3;
            int f4  = idx & 7;
            int k   = kk + f4 * 4;
            float4 va = make_float4(0.f, 0.f, 0.f, 0.f);
            if (k < IND) va = *(const float4*)(arow + (size_t)row * IND + k);
            As[f4 * 4 + 0][row] = va.x; As[f4 * 4 + 1][row] = va.y;
            As[f4 * 4 + 2][row] = va.z; As[f4 * 4 + 3][row] = va.w;
        }
        #pragma unroll
        for (int s = 0; s < 4; s++) {
            int idx = tid + s * 256;
            int row = idx >> 3;
            int f4  = idx & 7;
            int k   = kk + f4 * 4;
            float4 vb = make_float4(0.f, 0.f, 0.f, 0.f);
            if (k < IND) vb = *(const float4*)(win + (size_t)(n0 + row) * IND + k);
            Bs[f4 * 4 + 0][row] = vb.x; Bs[f4 * 4 + 1][row] = vb.y;
            Bs[f4 * 4 + 2][row] = vb.z; Bs[f4 * 4 + 3][row] = vb.w;
        }
        __syncthreads();

        #pragma unroll
        for (int k = 0; k < KT; k++) {
            float4 a  = *(const float4*)&As[k][ty * 4];
            float4 b0 = *(const float4*)&Bs[k][tx * 8];
            float4 b1 = *(const float4*)&Bs[k][tx * 8 + 4];
            float av[4] = {a.x, a.y, a.z, a.w};
            float bv[8] = {b0.x, b0.y, b0.z, b0.w, b1.x, b1.y, b1.z, b1.w};
            #pragma unroll
            for (int i = 0; i < 4; i++)
                #pragma unroll
                for (int j = 0; j < 8; j++)
                    acc[i][j] = fmaf(av[i], bv[j], acc[i][j]);
        }
        __syncthreads();
    }

    const int n = n0 + tx * 8;
    float4 bv0 = *(const float4*)(bias + n);
    float4 bv1 = *(const float4*)(bias + n + 4);
    #pragma unroll
    for (int i = 0; i < 4; i++) {
        int b = ty * 4 + i;
        float4 v0, v1;
        v0.x = acc[i][0] + bv0.x; v0.y = acc[i][1] + bv0.y;
        v0.z = acc[i][2] + bv0.z; v0.w = acc[i][3] + bv0.w;
        v1.x = acc[i][4] + bv1.x; v1.y = acc[i][5] + bv1.y;
        v1.z = acc[i][6] + bv1.z; v1.w = acc[i][7] + bv1.w;
        *(float4*)(out + (size_t)b * TD + (size_t)t * DIM + n)     = v0;
        *(float4*)(out + (size_t)b * TD + (size_t)t * DIM + n + 4) = v1;
    }
}

// ---------------------------------------------------------------------------
// rec_kernel: persistent recurrence, full-K per thread (no split-K).
//   128 CTAs = 2 halves x 64 d-tiles(16). 256 threads = 32 b x 8 dq.
//   Thread (b,dq) computes out[b0+b][t][d0+2dq .. +1] over full K=1024.
//   Warp w owns batch rows 4w..4w+3. Each thread stages its full 128-float
//   share of row b via 32 cp.asyncs in 4 groups of 8 (cols dq*4 + i*32);
//   compute waits per group at WARP scope -> staging pipelines into compute,
//   zero CTA-level syncs in the step body except the grid barrier.
// ---------------------------------------------------------------------------
__global__ void __launch_bounds__(256, 1) rec_kernel(const float* __restrict__ lw,
                                                     const float* __restrict__ init,
                                                     float* __restrict__ out) {
    extern __shared__ float sm[];
    float* xs    = sm;                 // 32 rows x XST floats
    float* wpack = sm + 32 * XST;      // 256 kq x 8 dq x 8 floats = 16384

    const int cta  = blockIdx.x;
    const int half = cta >> 6;
    const int b0   = half * 32;
    const int d0   = (cta & 63) * 16;
    const int tid  = threadIdx.x;
    const int b    = tid >> 3;         // 0..31
    const int dq   = tid & 7;          // 0..7

    // ---- build wpack once: wpack[kq*64 + dq*8 + c] ----
    // c=0..3 -> W[d0+2dq][4kq+c]; c=4..7 -> W[d0+2dq+1][4kq+c-4]
    for (int idx = tid; idx < 16384; idx += 256) {
        int kq = idx >> 6;
        int rest = idx & 63;
        int dqq = rest >> 3;
        int c = rest & 7;
        int d = 2 * dqq + (c >> 2);
        int k = 4 * kq + (c & 3);
        wpack[idx] = lw[(size_t)(d0 + d) * DIM + k];
    }
    __syncthreads();

    const int len = g_len[b0 + b];
    float* orow = out + (size_t)(b0 + b) * TD + (d0 + 2 * dq);
    const float* xrow = xs + b * XST;
    const float* wp = wpack + dq * 8;
    const unsigned xs_row_u32 = (unsigned)__cvta_generic_to_shared(xs)
                              + (unsigned)(b * XST * 4) + (unsigned)(dq * 16);
    unsigned* ctr_base = &g_bar[half * T_MAX];

    for (int t = 0; t < T_MAX; t++) {
        // ---- u prefetch (step-t data, independent of the barrier) ----
        float2 uv = __ldcg((const float2*)(orow + (size_t)t * DIM));

        // ---- stage this thread's full share of row b: cols dq*4 + i*32 ----
        if (t == 0) {
            #pragma unroll
            for (int i = 0; i < 32; i++) {
                float4 v = *(const float4*)(init + dq * 4 + i * 32);
                *(float4*)(xs + b * XST + dq * 4 + i * 32) = v;
            }
            __syncwarp();
        } else {
            const float* src = out + (size_t)(b0 + b) * TD + (size_t)(t - 1) * DIM + dq * 4;
            #pragma unroll
            for (int g = 0; g < 4; g++) {
                #pragma unroll
                for (int j = 0; j < 8; j++) {
                    int i = g * 8 + j;
                    asm volatile("cp.async.cg.shared.global [%0], [%1], 16;"
                                 :: "r"(xs_row_u32 + (unsigned)(i * 128)),
                                    "l"(src + i * 32) : "memory");
                }
                asm volatile("cp.async.commit_group;" ::: "memory");
            }
        }

        // ---- full-K dot products, consuming staged column groups in order ----
        unsigned long long z0a = 0ull, z0b = 0ull, z1a = 0ull, z1b = 0ull;
        #pragma unroll
        for (int g = 0; g < 4; g++) {
            if (t != 0) {
                if      (g == 0) asm volatile("cp.async.wait_group 3;" ::: "memory");
                else if (g == 1) asm volatile("cp.async.wait_group 2;" ::: "memory");
                else if (g == 2) asm volatile("cp.async.wait_group 1;" ::: "memory");
                else             asm volatile("cp.async.wait_group 0;" ::: "memory");
                __syncwarp();
            }
            #pragma unroll 8
            for (int kq = g * 64; kq < g * 64 + 64; kq++) {
                ulonglong2 xv = *(const ulonglong2*)(xrow + 4 * kq);
                ulonglong2 w0 = *(const ulonglong2*)(wp + 64 * kq);
                ulonglong2 w1 = *(const ulonglong2*)(wp + 64 * kq + 4);
                z0a = fma2(xv.x, w0.x, z0a);
                z0b = fma2(xv.y, w0.y, z0b);
                z1a = fma2(xv.x, w1.x, z1a);
                z1b = fma2(xv.y, w1.y, z1b);
            }
        }
        F2U s0, s1;
        s0.u = add2(z0a, z0b);
        s1.u = add2(z1a, z1b);
        float sum0 = s0.f.x + s0.f.y;
        float sum1 = s1.f.x + s1.f.y;

        // ---- epilogue ----
        {
            float2 xo = *(const float2*)(xrow + d0 + 2 * dq);
            float m = (t < len) ? 1.f : 0.f;
            float2 y;
            y.x = (0.5f * tanhf(uv.x + sum0) + 0.5f * xo.x) * m;
            y.y = (0.5f * tanhf(uv.y + sum1) + 0.5f * xo.y) * m;
            *(float2*)(orow + (size_t)t * DIM) = y;
        }

        // ---- per-half grid barrier ----
        __syncthreads();
        if (tid == 0) {
            unsigned* ctr = ctr_base + t;
            asm volatile("red.release.gpu.global.add.u32 [%0], 1;" :: "l"(ctr) : "memory");
            unsigned v;
            do {
                asm volatile("ld.relaxed.gpu.global.u32 %0, [%1];" : "=r"(v) : "l"(ctr) : "memory");
            } while (v < HALF_CTAS);
            asm volatile("ld.acquire.gpu.global.u32 %0, [%1];" : "=r"(v) : "l"(ctr) : "memory");
        }
        __syncthreads();
    }
}

// ---------------------------------------------------------------------------
extern "C" void kernel_launch(void* const* d_in, const int* in_sizes, int n_in,
                              void* d_out, int out_size) {
    const float* emb  = (const float*)d_in[0];
    const float* win  = (const float*)d_in[1];
    const float* lw   = (const float*)d_in[2];
    const float* bias = (const float*)d_in[3];
    const float* init = (const float*)d_in[4];
    float* out = (float*)d_out;

    zero_kernel<<<2, 512>>>();
    prep_kernel<<<512, 256>>>(emb);

    dim3 g(T_MAX, DIM / 128);
    ugemm_kernel<<<g, 256>>>(emb, win, bias, out);

    int smem = (32 * XST + 16384) * (int)sizeof(float);   // ~193 KB
    cudaFuncSetAttribute(rec_kernel, cudaFuncAttributeMaxDynamicSharedMemorySize, smem);
    rec_kernel<<<NCTA, 256, smem>>>(lw, init, out);

    tail_kernel<<<1, 64>>>(out, out_size);
}

// round 8
// speedup vs baseline: 2.2292x; 2.2292x over previous
#include <cuda_runtime.h>
#include <cstdint>

#define T_MAX 512
#define B_SZ  64
#define IND   300
#define DIM   1024
#define TD    (T_MAX * DIM)
#define NCTA  128
#define HALF_CTAS 64
#define PST   33
#define PROW  (16 * PST)          // 528

__device__ unsigned g_flag[2 * T_MAX * HALF_CTAS];   // per-(half,t,cta) arrival flags
__device__ int      g_len[B_SZ];

union F2U { float2 f; unsigned long long u; };

__device__ __forceinline__ unsigned long long fma2(unsigned long long a,
                                                   unsigned long long b,
                                                   unsigned long long c) {
    unsigned long long d;
    asm("fma.rn.f32x2 %0, %1, %2, %3;" : "=l"(d) : "l"(a), "l"(b), "l"(c));
    return d;
}
__device__ __forceinline__ unsigned long long add2(unsigned long long a,
                                                   unsigned long long b) {
    unsigned long long d;
    asm("add.rn.f32x2 %0, %1, %2;" : "=l"(d) : "l"(a), "l"(b));
    return d;
}

// ---------------------------------------------------------------------------
__global__ void zero_kernel() {
    int i = blockIdx.x * blockDim.x + threadIdx.x;
    if (i < 2 * T_MAX * HALF_CTAS) g_flag[i] = 0u;
    if (i < B_SZ)                  g_len[i] = 0;
}

// ---------------------------------------------------------------------------
__global__ void __launch_bounds__(256) prep_kernel(const float* __restrict__ emb) {
    int b  = blockIdx.x & 63;
    int tq = blockIdx.x >> 6;
    int row = threadIdx.x >> 2;
    int l4  = threadIdx.x & 3;
    int t = tq * 64 + row;
    const float* p = emb + ((size_t)t * B_SZ + b) * IND;
    float s = 0.f;
    for (int i = l4; i < IND; i += 4) s += p[i];
    s += __shfl_xor_sync(~0u, s, 1);
    s += __shfl_xor_sync(~0u, s, 2);
    unsigned ball = __ballot_sync(~0u, (l4 == 0) && (s != 0.f));
    if ((threadIdx.x & 31) == 0) atomicAdd(&g_len[b], __popc(ball));
}

// ---------------------------------------------------------------------------
__global__ void tail_kernel(float* __restrict__ out, int out_size) {
    int b = threadIdx.x;
    long long tail = (long long)T_MAX * B_SZ * DIM;
    if (b < B_SZ && (long long)out_size >= tail + B_SZ)
        out[tail + b] = (float)g_len[b];
}

// ---------------------------------------------------------------------------
// ugemm: u[t,b,:] = input_w @ emb[t,b,:] + bias -> out[b,t,:]
// Tile 64m x 128n; micro 8m x 4n (tx=0..31 over n, ty=0..7 over m).
// A read = warp broadcast; B read = 32 consecutive 16B -> conflict-free.
// ---------------------------------------------------------------------------
#define KT 32
__global__ void __launch_bounds__(256) ugemm_kernel(const float* __restrict__ emb,
                                                    const float* __restrict__ win,
                                                    const float* __restrict__ bias,
                                                    float* __restrict__ out) {
    __shared__ float As[KT][68];
    __shared__ float Bs[KT][136];

    const int t  = blockIdx.x;
    const int n0 = blockIdx.y * 128;
    const int tid = threadIdx.x;
    const int tx = tid & 31, ty = tid >> 5;
    const float* arow = emb + (size_t)t * B_SZ * IND;

    float acc[8][4];
    #pragma unroll
    for (int i = 0; i < 8; i++)
        #pragma unroll
        for (int j = 0; j < 4; j++) acc[i][j] = 0.f;

    for (int kk = 0; kk < IND; kk += KT) {
        #pragma unroll
        for (int s = 0; s < 2; s++) {
            int idx = tid + s * 256;
            int row = idx >> 3;
            int f4  = idx & 7;
            int k   = kk + f4 * 4;
            float4 va = make_float4(0.f, 0.f, 0.f, 0.f);
            if (k < IND) va = *(const float4*)(arow + (size_t)row * IND + k);
            As[f4 * 4 + 0][row] = va.x; As[f4 * 4 + 1][row] = va.y;
            As[f4 * 4 + 2][row] = va.z; As[f4 * 4 + 3][row] = va.w;
        }
        #pragma unroll
        for (int s = 0; s < 4; s++) {
            int idx = tid + s * 256;
            int row = idx >> 3;
            int f4  = idx & 7;
            int k   = kk + f4 * 4;
            float4 vb = make_float4(0.f, 0.f, 0.f, 0.f);
            if (k < IND) vb = *(const float4*)(win + (size_t)(n0 + row) * IND + k);
            Bs[f4 * 4 + 0][row] = vb.x; Bs[f4 * 4 + 1][row] = vb.y;
            Bs[f4 * 4 + 2][row] = vb.z; Bs[f4 * 4 + 3][row] = vb.w;
        }
        __syncthreads();

        #pragma unroll
        for (int k = 0; k < KT; k++) {
            float4 a0 = *(const float4*)&As[k][ty * 8];
            float4 a1 = *(const float4*)&As[k][ty * 8 + 4];
            float4 bv = *(const float4*)&Bs[k][tx * 4];
            float av[8] = {a0.x, a0.y, a0.z, a0.w, a1.x, a1.y, a1.z, a1.w};
            float bb[4] = {bv.x, bv.y, bv.z, bv.w};
            #pragma unroll
            for (int i = 0; i < 8; i++)
                #pragma unroll
                for (int j = 0; j < 4; j++)
                    acc[i][j] = fmaf(av[i], bb[j], acc[i][j]);
        }
        __syncthreads();
    }

    const int n = n0 + tx * 4;
    float4 bv = *(const float4*)(bias + n);
    #pragma unroll
    for (int i = 0; i < 8; i++) {
        int b = ty * 8 + i;
        float4 v;
        v.x = acc[i][0] + bv.x; v.y = acc[i][1] + bv.y;
        v.z = acc[i][2] + bv.z; v.w = acc[i][3] + bv.w;
        *(float4*)(out + (size_t)b * TD + (size_t)t * DIM + n) = v;
    }
}

// ---------------------------------------------------------------------------
// rec_kernel: persistent recurrence (R5 split-K layout + warp-local staging).
//   128 CTAs = 2 halves x 64 d-tiles(16). 256 threads = 32 ks x 8 td.
//   Thread (ks,td): partial dots over k in [32ks,32ks+32) for all 32 b rows,
//   outputs row b0+ks, dims d0+2td..+1 after smem split-K reduction.
//   Warp w consumes only k in [128w,128w+128) -> stages exactly those columns
//   itself (cp.async, 4 groups of 8 rows), syncs at warp scope only.
//   x_old for the leak term = thread's own previous y (register carry).
//   Grid barrier: per-(t,cta) release flags + 64-thread parallel poll.
// ---------------------------------------------------------------------------
__global__ void __launch_bounds__(256, 1) rec_kernel(const float* __restrict__ lw,
                                                     const float* __restrict__ init,
                                                     float* __restrict__ out) {
    extern __shared__ float sm[];
    float* xs = sm;                  // 32 x 1024 (rotation-swizzled)
    float* ps = sm + 32 * 1024;      // partials 32 x PROW

    const int cta  = blockIdx.x;
    const int half = cta >> 6;
    const int lcta = cta & 63;
    const int b0   = half * 32;
    const int d0   = lcta * 16;
    const int tid  = threadIdx.x;
    const int ks   = tid >> 3;       // 0..31
    const int td   = tid & 7;        // 0..7
    const int w    = tid >> 5;       // warp 0..7
    const int lane = tid & 31;
    const int kb   = ks * 32;

    // ---- W tile into registers as f32x2 pairs ----
    unsigned long long w0p[16], w1p[16];
    {
        const float* r0 = lw + (size_t)(d0 + 2 * td) * DIM + kb;
        const float* r1 = r0 + DIM;
        #pragma unroll
        for (int q = 0; q < 8; q++) {
            float4 a = *(const float4*)(r0 + 4 * q);
            float4 b = *(const float4*)(r1 + 4 * q);
            F2U t0, t1, t2, t3;
            t0.f = make_float2(a.x, a.y); t1.f = make_float2(a.z, a.w);
            t2.f = make_float2(b.x, b.y); t3.f = make_float2(b.z, b.w);
            w0p[2 * q] = t0.u; w0p[2 * q + 1] = t1.u;
            w1p[2 * q] = t2.u; w1p[2 * q + 1] = t3.u;
        }
    }

    // rotated load offsets for compute (slice index == ks)
    int off[8];
    #pragma unroll
    for (int q = 0; q < 8; q++) off[q] = (((q + ks) & 7) << 2);

    // staging geometry: this lane handles slice s_sl (of warp w's 4 slices),
    // quad s_c within the slice, for every row.
    const int s_sl = 4 * w + (lane >> 3);            // 0..31
    const int s_c  = lane & 7;
    const int src_col = s_sl * 32 + s_c * 4;         // source column (float idx)
    const int dst_off = s_sl * 32 + (((s_c + s_sl) & 7) << 2);
    const unsigned xs_u32 = (unsigned)__cvta_generic_to_shared(xs);

    const int len = g_len[b0 + ks];
    const int kx0 = d0 + 2 * td;
    float* orow = out + (size_t)(b0 + ks) * TD + kx0;

    // register-carried state: own previous output + prefetched u
    float2 xo = *(const float2*)(init + kx0);
    float2 uv = __ldcg((const float2*)orow);

    unsigned* flag_base = &g_flag[(half * T_MAX) * HALF_CTAS];

    for (int t = 0; t < T_MAX; t++) {
        // ---- stage x_{t-1}: warp-local columns, 4 groups of 8 rows ----
        if (t == 0) {
            float4 v = *(const float4*)(init + src_col);
            #pragma unroll 8
            for (int i = 0; i < 32; i++)
                *(float4*)(xs + i * 1024 + dst_off) = v;
        } else {
            const float* src = out + (size_t)b0 * TD + (size_t)(t - 1) * DIM + src_col;
            #pragma unroll
            for (int g = 0; g < 4; g++) {
                #pragma unroll
                for (int j = 0; j < 8; j++) {
                    int i = g * 8 + j;
                    asm volatile("cp.async.cg.shared.global [%0], [%1], 16;"
                                 :: "r"(xs_u32 + (unsigned)((i * 1024 + dst_off) * 4)),
                                    "l"(src + (size_t)i * TD) : "memory");
                }
                asm volatile("cp.async.commit_group;" ::: "memory");
            }
        }

        // ---- compute partial dots, consuming row groups in order ----
        #pragma unroll
        for (int g = 0; g < 4; g++) {
            if      (g == 0) asm volatile("cp.async.wait_group 3;" ::: "memory");
            else if (g == 1) asm volatile("cp.async.wait_group 2;" ::: "memory");
            else if (g == 2) asm volatile("cp.async.wait_group 1;" ::: "memory");
            else             asm volatile("cp.async.wait_group 0;" ::: "memory");
            __syncwarp();
            #pragma unroll
            for (int bb = 0; bb < 8; bb++) {
                int b = g * 8 + bb;
                const float* xr = xs + b * 1024 + kb;
                unsigned long long a0a = 0ull, a0b = 0ull, a1a = 0ull, a1b = 0ull;
                #pragma unroll
                for (int q = 0; q < 8; q++) {
                    ulonglong2 v = *(const ulonglong2*)(xr + off[q]);
                    a0a = fma2(v.x, w0p[2 * q],     a0a);
                    a0b = fma2(v.y, w0p[2 * q + 1], a0b);
                    a1a = fma2(v.x, w1p[2 * q],     a1a);
                    a1b = fma2(v.y, w1p[2 * q + 1], a1b);
                }
                F2U s0, s1;
                s0.u = add2(a0a, a0b);
                s1.u = add2(a1a, a1b);
                ps[b * PROW + (2 * td)     * PST + ks] = s0.f.x + s0.f.y;
                ps[b * PROW + (2 * td + 1) * PST + ks] = s1.f.x + s1.f.y;
            }
        }
        __syncthreads();

        // ---- split-K reduction + epilogue ----
        float s0 = 0.f, s1 = 0.f;
        {
            const float* p0 = ps + ks * PROW + (2 * td) * PST;
            const float* p1 = p0 + PST;
            #pragma unroll
            for (int i = 0; i < 32; i++) { s0 += p0[i]; s1 += p1[i]; }
        }
        {
            float m = (t < len) ? 1.f : 0.f;
            float2 y;
            y.x = (0.5f * tanhf(uv.x + s0) + 0.5f * xo.x) * m;
            y.y = (0.5f * tanhf(uv.y + s1) + 0.5f * xo.y) * m;
            *(float2*)(orow + (size_t)t * DIM) = y;
            xo = y;
        }
        // prefetch next step's u (hidden under the barrier)
        {
            int tn = (t + 1 < T_MAX) ? t + 1 : t;
            uv = __ldcg((const float2*)(orow + (size_t)tn * DIM));
        }

        // ---- flag-based per-half grid barrier ----
        __syncthreads();
        unsigned* flags = flag_base + t * HALF_CTAS;
        if (tid == 0) {
            asm volatile("st.release.gpu.global.u32 [%0], 1;"
                         :: "l"(flags + lcta) : "memory");
        }
        if (tid < HALF_CTAS) {
            const unsigned* f = flags + tid;
            unsigned v;
            do {
                asm volatile("ld.relaxed.gpu.global.u32 %0, [%1];" : "=r"(v) : "l"(f) : "memory");
            } while (v == 0u);
            asm volatile("ld.acquire.gpu.global.u32 %0, [%1];" : "=r"(v) : "l"(f) : "memory");
        }
        __syncthreads();
    }
}

// ---------------------------------------------------------------------------
extern "C" void kernel_launch(void* const* d_in, const int* in_sizes, int n_in,
                              void* d_out, int out_size) {
    const float* emb  = (const float*)d_in[0];
    const float* win  = (const float*)d_in[1];
    const float* lw   = (const float*)d_in[2];
    const float* bias = (const float*)d_in[3];
    const float* init = (const float*)d_in[4];
    float* out = (float*)d_out;

    zero_kernel<<<(2 * T_MAX * HALF_CTAS + 255) / 256, 256>>>();
    prep_kernel<<<512, 256>>>(emb);

    dim3 g(T_MAX, DIM / 128);
    ugemm_kernel<<<g, 256>>>(emb, win, bias, out);

    int smem = (32 * 1024 + 32 * PROW) * (int)sizeof(float);   // ~194 KB
    cudaFuncSetAttribute(rec_kernel, cudaFuncAttributeMaxDynamicSharedMemorySize, smem);
    rec_kernel<<<NCTA, 256, smem>>>(lw, init, out);

    tail_kernel<<<1, 64>>>(out, out_size);
}

// round 10
// speedup vs baseline: 2.9569x; 1.3265x over previous
#include <cuda_runtime.h>
#include <cstdint>

#define T_MAX 512
#define B_SZ  64
#define IND   300
#define DIM   1024
#define TD    (T_MAX * DIM)
#define NCTA  128
#define HALF_CTAS 64
#define PST   33
#define PROW  (16 * PST)

__device__ unsigned g_bar[2 * T_MAX];
__device__ int      g_len[B_SZ];

union F2U { float2 f; unsigned long long u; };

__device__ __forceinline__ unsigned long long fma2(unsigned long long a,
                                                   unsigned long long b,
                                                   unsigned long long c) {
    unsigned long long d;
    asm("fma.rn.f32x2 %0, %1, %2, %3;" : "=l"(d) : "l"(a), "l"(b), "l"(c));
    return d;
}
__device__ __forceinline__ unsigned long long add2(unsigned long long a,
                                                   unsigned long long b) {
    unsigned long long d;
    asm("add.rn.f32x2 %0, %1, %2;" : "=l"(d) : "l"(a), "l"(b));
    return d;
}

// ---------------------------------------------------------------------------
__global__ void zero_kernel() {
    int i = blockIdx.x * blockDim.x + threadIdx.x;
    if (i < 2 * T_MAX) g_bar[i] = 0u;
    if (i < B_SZ)      g_len[i] = 0;
}

// ---------------------------------------------------------------------------
__global__ void __launch_bounds__(256) prep_kernel(const float* __restrict__ emb) {
    int b  = blockIdx.x & 63;
    int tq = blockIdx.x >> 6;
    int row = threadIdx.x >> 2;
    int l4  = threadIdx.x & 3;
    int t = tq * 64 + row;
    const float* p = emb + ((size_t)t * B_SZ + b) * IND;
    float s = 0.f;
    for (int i = l4; i < IND; i += 4) s += p[i];
    s += __shfl_xor_sync(~0u, s, 1);
    s += __shfl_xor_sync(~0u, s, 2);
    unsigned ball = __ballot_sync(~0u, (l4 == 0) && (s != 0.f));
    if ((threadIdx.x & 31) == 0) atomicAdd(&g_len[b], __popc(ball));
}

// ---------------------------------------------------------------------------
__global__ void tail_kernel(float* __restrict__ out, int out_size) {
    int b = threadIdx.x;
    long long tail = (long long)T_MAX * B_SZ * DIM;
    if (b < B_SZ && (long long)out_size >= tail + B_SZ)
        out[tail + b] = (float)g_len[b];
}

// ---------------------------------------------------------------------------
// ugemm: u[t,b,:] = input_w @ emb[t,b,:] + bias -> out[b,t,:]  (R5 version)
// ---------------------------------------------------------------------------
#define KT 32
__global__ void __launch_bounds__(256) ugemm_kernel(const float* __restrict__ emb,
                                                    const float* __restrict__ win,
                                                    const float* __restrict__ bias,
                                                    float* __restrict__ out) {
    __shared__ float As[KT][68];
    __shared__ float Bs[KT][136];

    const int t  = blockIdx.x;
    const int n0 = blockIdx.y * 128;
    const int tid = threadIdx.x;
    const int tx = tid & 15, ty = tid >> 4;
    const float* arow = emb + (size_t)t * B_SZ * IND;

    float acc[4][8];
    #pragma unroll
    for (int i = 0; i < 4; i++)
        #pragma unroll
        for (int j = 0; j < 8; j++) acc[i][j] = 0.f;

    for (int kk = 0; kk < IND; kk += KT) {
        #pragma unroll
        for (int s = 0; s < 2; s++) {
            int idx = tid + s * 256;
            int row = idx >> 3;
            int f4  = idx & 7;
            int k   = kk + f4 * 4;
            float4 va = make_float4(0.f, 0.f, 0.f, 0.f);
            if (k < IND) va = *(const float4*)(arow + (size_t)row * IND + k);
            As[f4 * 4 + 0][row] = va.x; As[f4 * 4 + 1][row] = va.y;
            As[f4 * 4 + 2][row] = va.z; As[f4 * 4 + 3][row] = va.w;
        }
        #pragma unroll
        for (int s = 0; s < 4; s++) {
            int idx = tid + s * 256;
            int row = idx >> 3;
            int f4  = idx & 7;
            int k   = kk + f4 * 4;
            float4 vb = make_float4(0.f, 0.f, 0.f, 0.f);
            if (k < IND) vb = *(const float4*)(win + (size_t)(n0 + row) * IND + k);
            Bs[f4 * 4 + 0][row] = vb.x; Bs[f4 * 4 + 1][row] = vb.y;
            Bs[f4 * 4 + 2][row] = vb.z; Bs[f4 * 4 + 3][row] = vb.w;
        }
        __syncthreads();

        #pragma unroll
        for (int k = 0; k < KT; k++) {
            float4 a  = *(const float4*)&As[k][ty * 4];
            float4 b0 = *(const float4*)&Bs[k][tx * 8];
            float4 b1 = *(const float4*)&Bs[k][tx * 8 + 4];
            float av[4] = {a.x, a.y, a.z, a.w};
            float bv[8] = {b0.x, b0.y, b0.z, b0.w, b1.x, b1.y, b1.z, b1.w};
            #pragma unroll
            for (int i = 0; i < 4; i++)
                #pragma unroll
                for (int j = 0; j < 8; j++)
                    acc[i][j] = fmaf(av[i], bv[j], acc[i][j]);
        }
        __syncthreads();
    }

    const int n = n0 + tx * 8;
    float4 bv0 = *(const float4*)(bias + n);
    float4 bv1 = *(const float4*)(bias + n + 4);
    #pragma unroll
    for (int i = 0; i < 4; i++) {
        int b = ty * 4 + i;
        float4 v0, v1;
        v0.x = acc[i][0] + bv0.x; v0.y = acc[i][1] + bv0.y;
        v0.z = acc[i][2] + bv0.z; v0.w = acc[i][3] + bv0.w;
        v1.x = acc[i][4] + bv1.x; v1.y = acc[i][5] + bv1.y;
        v1.z = acc[i][6] + bv1.z; v1.w = acc[i][7] + bv1.w;
        *(float4*)(out + (size_t)b * TD + (size_t)t * DIM + n)     = v0;
        *(float4*)(out + (size_t)b * TD + (size_t)t * DIM + n + 4) = v1;
    }
}

// ---------------------------------------------------------------------------
// rec_kernel: R5 structure. 128 CTAs = 2 halves x 64 d-tiles(16).
//   256 threads = 32 ks x 8 td. Changes vs R5:
//   - chunk waits at warp scope (consumed data is staged by the same warp),
//   - leak term carried in a register,
//   - u[t+1] prefetch before the barrier.
//   Reduction: R5's scalar version (alignment-safe).
//   Barrier: R5's per-half single counter (measured good).
// ---------------------------------------------------------------------------
__global__ void __launch_bounds__(256, 1) rec_kernel(const float* __restrict__ lw,
                                                     const float* __restrict__ init,
                                                     float* __restrict__ out) {
    extern __shared__ float sm[];
    float* xs = sm;                 // 32 * 1024 floats (swizzled)
    float* ps = sm + 32 * 1024;     // partials

    const int cta  = blockIdx.x;
    const int half = cta >> 6;
    const int b0   = half * 32;
    const int d0   = (cta & 63) * 16;
    const int tid  = threadIdx.x;
    const int ks   = tid >> 3;
    const int td   = tid & 7;
    const int kb   = ks * 32;

    // W tile into registers as f32x2 pairs
    unsigned long long w0p[16], w1p[16];
    {
        const float* r0 = lw + (size_t)(d0 + 2 * td) * DIM + kb;
        const float* r1 = r0 + DIM;
        #pragma unroll
        for (int q = 0; q < 8; q++) {
            float4 a = *(const float4*)(r0 + 4 * q);
            float4 b = *(const float4*)(r1 + 4 * q);
            F2U t0, t1, t2, t3;
            t0.f = make_float2(a.x, a.y); t1.f = make_float2(a.z, a.w);
            t2.f = make_float2(b.x, b.y); t3.f = make_float2(b.z, b.w);
            w0p[2 * q] = t0.u; w0p[2 * q + 1] = t1.u;
            w1p[2 * q] = t2.u; w1p[2 * q + 1] = t3.u;
        }
    }

    int off[8];
    #pragma unroll
    for (int q = 0; q < 8; q++) off[q] = (((q + ks) & 7) << 2);

    const int st_slice = tid >> 3;
    const int st_pos   = tid & 7;
    const int st_off   = st_slice * 32 + (((st_pos + st_slice) & 7) << 2);
    const unsigned xs_u32 = (unsigned)__cvta_generic_to_shared(xs) + (unsigned)(st_off * 4);

    const int len = g_len[b0 + ks];
    const int kx0 = d0 + 2 * td;
    float* orow = out + (size_t)(b0 + ks) * TD + kx0;
    unsigned* ctr_base = &g_bar[half * T_MAX];

    // register-carried state: own previous output + prefetched u
    float2 xo = *(const float2*)(init + kx0);
    float2 uv = __ldcg((const float2*)orow);

    for (int t = 0; t < T_MAX; t++) {
        // ---- stage x_{t-1}: this thread's column (tid*4) for all 32 rows ----
        if (t == 0) {
            float4 v = *(const float4*)(init + tid * 4);
            #pragma unroll 4
            for (int s = 0; s < 32; s++)
                *(float4*)&xs[s * 1024 + st_off] = v;
            __syncwarp();
        } else {
            const float* src = out + (size_t)b0 * TD + (size_t)(t - 1) * DIM + tid * 4;
            #pragma unroll
            for (int s = 0; s < 32; s++) {
                asm volatile("cp.async.cg.shared.global [%0], [%1], 16;"
                             :: "r"(xs_u32 + (unsigned)(s * 4096)),
                                "l"(src + (size_t)s * TD) : "memory");
                if ((s & 7) == 7) asm volatile("cp.async.commit_group;" ::: "memory");
            }
        }

        // ---- compute partials, consuming staged chunks (warp-local data) ----
        #pragma unroll
        for (int c = 0; c < 4; c++) {
            if (t != 0) {
                if      (c == 0) asm volatile("cp.async.wait_group 3;" ::: "memory");
                else if (c == 1) asm volatile("cp.async.wait_group 2;" ::: "memory");
                else if (c == 2) asm volatile("cp.async.wait_group 1;" ::: "memory");
                else             asm volatile("cp.async.wait_group 0;" ::: "memory");
                __syncwarp();
            }
            const float* xr = xs + (size_t)(c * 8) * 1024 + kb;
            #pragma unroll
            for (int bb = 0; bb < 8; bb++) {
                int b = c * 8 + bb;
                unsigned long long a0a = 0ull, a0b = 0ull, a1a = 0ull, a1b = 0ull;
                #pragma unroll
                for (int q = 0; q < 8; q++) {
                    ulonglong2 v = *(const ulonglong2*)(xr + off[q]);
                    a0a = fma2(v.x, w0p[2 * q],     a0a);
                    a0b = fma2(v.y, w0p[2 * q + 1], a0b);
                    a1a = fma2(v.x, w1p[2 * q],     a1a);
                    a1b = fma2(v.y, w1p[2 * q + 1], a1b);
                }
                F2U s0, s1;
                s0.u = add2(a0a, a0b);
                s1.u = add2(a1a, a1b);
                ps[b * PROW + (2 * td)     * PST + ks] = s0.f.x + s0.f.y;
                ps[b * PROW + (2 * td + 1) * PST + ks] = s1.f.x + s1.f.y;
                xr += 1024;
            }
        }
        __syncthreads();

        // ---- split-K reduction (scalar, alignment-safe) ----
        float sum0 = 0.f, sum1 = 0.f;
        {
            const float* p0 = ps + ks * PROW + (2 * td) * PST;
            const float* p1 = p0 + PST;
            #pragma unroll
            for (int i = 0; i < 32; i++) { sum0 += p0[i]; sum1 += p1[i]; }
        }

        // ---- epilogue: tanh + leak(register) + mask + store ----
        {
            float m = (t < len) ? 1.f : 0.f;
            float2 y;
            y.x = (0.5f * tanhf(uv.x + sum0) + 0.5f * xo.x) * m;
            y.y = (0.5f * tanhf(uv.y + sum1) + 0.5f * xo.y) * m;
            *(float2*)(orow + (size_t)t * DIM) = y;
            xo = y;
        }
        // prefetch next step's u (only this thread ever writes that address)
        {
            int tn = (t + 1 < T_MAX) ? t + 1 : t;
            uv = __ldcg((const float2*)(orow + (size_t)tn * DIM));
        }

        // ---- per-half grid barrier (R5's counter) ----
        __syncthreads();
        if (tid == 0) {
            unsigned* ctr = ctr_base + t;
            asm volatile("red.release.gpu.global.add.u32 [%0], 1;" :: "l"(ctr) : "memory");
            unsigned v;
            do {
                asm volatile("ld.relaxed.gpu.global.u32 %0, [%1];" : "=r"(v) : "l"(ctr) : "memory");
            } while (v < HALF_CTAS);
            asm volatile("ld.acquire.gpu.global.u32 %0, [%1];" : "=r"(v) : "l"(ctr) : "memory");
        }
        __syncthreads();
    }
}

// ---------------------------------------------------------------------------
extern "C" void kernel_launch(void* const* d_in, const int* in_sizes, int n_in,
                              void* d_out, int out_size) {
    const float* emb  = (const float*)d_in[0];
    const float* win  = (const float*)d_in[1];
    const float* lw   = (const float*)d_in[2];
    const float* bias = (const float*)d_in[3];
    const float* init = (const float*)d_in[4];
    float* out = (float*)d_out;

    zero_kernel<<<2, 512>>>();
    prep_kernel<<<512, 256>>>(emb);

    dim3 g(T_MAX, DIM / 128);
    ugemm_kernel<<<g, 256>>>(emb, win, bias, out);

    int smem = (32 * 1024 + 32 * PROW) * (int)sizeof(float);
    cudaFuncSetAttribute(rec_kernel, cudaFuncAttributeMaxDynamicSharedMemorySize, smem);
    rec_kernel<<<NCTA, 256, smem>>>(lw, init, out);

    tail_kernel<<<1, 64>>>(out, out_size);
}

// round 11
// speedup vs baseline: 3.6130x; 1.2219x over previous
#include <cuda_runtime.h>
#include <cstdint>

#define T_MAX 512
#define B_SZ  64
#define IND   300
#define DIM   1024
#define TD    (T_MAX * DIM)
#define NCTA  128
#define GRP_CTAS 32              // CTAs per batch-quarter group
#define NGRP  4
#define PST   33                 // partial stride (per output)

__device__ unsigned g_bar[NGRP * T_MAX];
__device__ int      g_len[B_SZ];

union F2U { float2 f; unsigned long long u; };

__device__ __forceinline__ unsigned long long fma2(unsigned long long a,
                                                   unsigned long long b,
                                                   unsigned long long c) {
    unsigned long long d;
    asm("fma.rn.f32x2 %0, %1, %2, %3;" : "=l"(d) : "l"(a), "l"(b), "l"(c));
    return d;
}
__device__ __forceinline__ unsigned long long add2(unsigned long long a,
                                                   unsigned long long b) {
    unsigned long long d;
    asm("add.rn.f32x2 %0, %1, %2;" : "=l"(d) : "l"(a), "l"(b));
    return d;
}

// ---------------------------------------------------------------------------
__global__ void zero_kernel() {
    int i = blockIdx.x * blockDim.x + threadIdx.x;
    if (i < NGRP * T_MAX) g_bar[i] = 0u;
    if (i < B_SZ)         g_len[i] = 0;
}

// ---------------------------------------------------------------------------
__global__ void __launch_bounds__(256) prep_kernel(const float* __restrict__ emb) {
    int b  = blockIdx.x & 63;
    int tq = blockIdx.x >> 6;
    int row = threadIdx.x >> 2;
    int l4  = threadIdx.x & 3;
    int t = tq * 64 + row;
    const float* p = emb + ((size_t)t * B_SZ + b) * IND;
    float s = 0.f;
    for (int i = l4; i < IND; i += 4) s += p[i];
    s += __shfl_xor_sync(~0u, s, 1);
    s += __shfl_xor_sync(~0u, s, 2);
    unsigned ball = __ballot_sync(~0u, (l4 == 0) && (s != 0.f));
    if ((threadIdx.x & 31) == 0) atomicAdd(&g_len[b], __popc(ball));
}

// ---------------------------------------------------------------------------
__global__ void tail_kernel(float* __restrict__ out, int out_size) {
    int b = threadIdx.x;
    long long tail = (long long)T_MAX * B_SZ * DIM;
    if (b < B_SZ && (long long)out_size >= tail + B_SZ)
        out[tail + b] = (float)g_len[b];
}

// ---------------------------------------------------------------------------
// ugemm (R8 tile): 64m x 128n, micro 8m x 4n; tx=0..31 (n), ty=0..7 (m).
// B-read: 8 lanes/phase hit distinct 16B chunks -> conflict-free LDS.128.
// A-read: ty constant within warp -> uniform broadcast.
// ---------------------------------------------------------------------------
#define KT 32
__global__ void __launch_bounds__(256) ugemm_kernel(const float* __restrict__ emb,
                                                    const float* __restrict__ win,
                                                    const float* __restrict__ bias,
                                                    float* __restrict__ out) {
    __shared__ float As[KT][68];
    __shared__ float Bs[KT][136];

    const int t  = blockIdx.x;
    const int n0 = blockIdx.y * 128;
    const int tid = threadIdx.x;
    const int tx = tid & 31, ty = tid >> 5;
    const float* arow = emb + (size_t)t * B_SZ * IND;

    float acc[8][4];
    #pragma unroll
    for (int i = 0; i < 8; i++)
        #pragma unroll
        for (int j = 0; j < 4; j++) acc[i][j] = 0.f;

    for (int kk = 0; kk < IND; kk += KT) {
        #pragma unroll
        for (int s = 0; s < 2; s++) {
            int idx = tid + s * 256;
            int row = idx >> 3;
            int f4  = idx & 7;
            int k   = kk + f4 * 4;
            float4 va = make_float4(0.f, 0.f, 0.f, 0.f);
            if (k < IND) va = *(const float4*)(arow + (size_t)row * IND + k);
            As[f4 * 4 + 0][row] = va.x; As[f4 * 4 + 1][row] = va.y;
            As[f4 * 4 + 2][row] = va.z; As[f4 * 4 + 3][row] = va.w;
        }
        #pragma unroll
        for (int s = 0; s < 4; s++) {
            int idx = tid + s * 256;
            int row = idx >> 3;
            int f4  = idx & 7;
            int k   = kk + f4 * 4;
            float4 vb = make_float4(0.f, 0.f, 0.f, 0.f);
            if (k < IND) vb = *(const float4*)(win + (size_t)(n0 + row) * IND + k);
            Bs[f4 * 4 + 0][row] = vb.x; Bs[f4 * 4 + 1][row] = vb.y;
            Bs[f4 * 4 + 2][row] = vb.z; Bs[f4 * 4 + 3][row] = vb.w;
        }
        __syncthreads();

        #pragma unroll
        for (int k = 0; k < KT; k++) {
            float4 a0 = *(const float4*)&As[k][ty * 8];
            float4 a1 = *(const float4*)&As[k][ty * 8 + 4];
            float4 bv = *(const float4*)&Bs[k][tx * 4];
            float av[8] = {a0.x, a0.y, a0.z, a0.w, a1.x, a1.y, a1.z, a1.w};
            float bb[4] = {bv.x, bv.y, bv.z, bv.w};
            #pragma unroll
            for (int i = 0; i < 8; i++)
                #pragma unroll
                for (int j = 0; j < 4; j++)
                    acc[i][j] = fmaf(av[i], bb[j], acc[i][j]);
        }
        __syncthreads();
    }

    const int n = n0 + tx * 4;
    float4 bv = *(const float4*)(bias + n);
    #pragma unroll
    for (int i = 0; i < 8; i++) {
        int b = ty * 8 + i;
        float4 v;
        v.x = acc[i][0] + bv.x; v.y = acc[i][1] + bv.y;
        v.z = acc[i][2] + bv.z; v.w = acc[i][3] + bv.w;
        *(float4*)(out + (size_t)b * TD + (size_t)t * DIM + n) = v;
    }
}

// ---------------------------------------------------------------------------
// rec_kernel: 128 CTAs = 4 batch-quarters(16 rows) x 32 d-CTAs(32 dims).
//   256 threads = 32 ks x 8 td. Thread (ks,td): partials for 4 dims
//   (d0+4td..+3) over k in [32ks,32ks+32) for all 16 rows.
//   W: 64 ull registers/thread. x: 16x1024 smem, rotation-swizzled.
//   Warp w stages cols [128w,128w+128) (its own ks slices) -> warp-scope
//   chunk waits. Reduction: thread reduces outputs 2*tid, 2*tid+1.
// ---------------------------------------------------------------------------
__global__ void __launch_bounds__(256, 1) rec_kernel(const float* __restrict__ lw,
                                                     const float* __restrict__ init,
                                                     float* __restrict__ out) {
    extern __shared__ float sm[];
    float* xs = sm;                 // 16 * 1024 floats (swizzled)
    float* ps = sm + 16 * 1024;     // partials: 512 outputs * PST

    const int cta  = blockIdx.x;
    const int grp  = cta >> 5;          // 0..3
    const int lcta = cta & 31;          // 0..31
    const int b0   = grp * 16;
    const int d0   = lcta * 32;
    const int tid  = threadIdx.x;
    const int ks   = tid >> 3;          // 0..31
    const int td   = tid & 7;           // 0..7
    const int kb   = ks * 32;

    // ---- W tile into registers: 4 dims x 32 k as f32x2 pairs ----
    unsigned long long wp[4][16];
    #pragma unroll
    for (int i = 0; i < 4; i++) {
        const float* r = lw + (size_t)(d0 + td * 4 + i) * DIM + kb;
        #pragma unroll
        for (int q = 0; q < 8; q++) {
            float4 a = *(const float4*)(r + 4 * q);
            F2U t0, t1;
            t0.f = make_float2(a.x, a.y); t1.f = make_float2(a.z, a.w);
            wp[i][2 * q] = t0.u; wp[i][2 * q + 1] = t1.u;
        }
    }

    int off[8];
    #pragma unroll
    for (int q = 0; q < 8; q++) off[q] = (((q + ks) & 7) << 2);

    // staging swizzle: this thread's column quad = tid (col tid*4)
    const int st_slice = tid >> 3;
    const int st_pos   = tid & 7;
    const int st_off   = st_slice * 32 + (((st_pos + st_slice) & 7) << 2);
    const unsigned xs_u32 = (unsigned)__cvta_generic_to_shared(xs) + (unsigned)(st_off * 4);

    // this thread's two reduced outputs: o = 2*tid, 2*tid+1 -> (b_r, d_r..d_r+1)
    const int b_r = tid >> 4;
    const int d_r = (2 * tid) & 31;
    const int len = g_len[b0 + b_r];
    float* orow = out + (size_t)(b0 + b_r) * TD + (d0 + d_r);
    unsigned* ctr_base = &g_bar[grp * T_MAX];

    float2 xo = *(const float2*)(init + d0 + d_r);
    float2 uv = __ldcg((const float2*)orow);

    for (int t = 0; t < T_MAX; t++) {
        // ---- stage x_{t-1}: this thread's column (tid*4) for 16 rows ----
        if (t == 0) {
            float4 v = *(const float4*)(init + tid * 4);
            #pragma unroll 4
            for (int r = 0; r < 16; r++)
                *(float4*)&xs[r * 1024 + st_off] = v;
            __syncwarp();
        } else {
            const float* src = out + (size_t)b0 * TD + (size_t)(t - 1) * DIM + tid * 4;
            #pragma unroll
            for (int r = 0; r < 16; r++) {
                asm volatile("cp.async.cg.shared.global [%0], [%1], 16;"
                             :: "r"(xs_u32 + (unsigned)(r * 4096)),
                                "l"(src + (size_t)r * TD) : "memory");
                if ((r & 3) == 3) asm volatile("cp.async.commit_group;" ::: "memory");
            }
        }

        // ---- compute partials: chunks of 4 rows, warp-scope waits ----
        #pragma unroll
        for (int c = 0; c < 4; c++) {
            if (t != 0) {
                if      (c == 0) asm volatile("cp.async.wait_group 3;" ::: "memory");
                else if (c == 1) asm volatile("cp.async.wait_group 2;" ::: "memory");
                else if (c == 2) asm volatile("cp.async.wait_group 1;" ::: "memory");
                else             asm volatile("cp.async.wait_group 0;" ::: "memory");
                __syncwarp();
            }
            #pragma unroll
            for (int rr = 0; rr < 4; rr++) {
                int b = c * 4 + rr;
                const float* xr = xs + b * 1024 + kb;
                unsigned long long a0a = 0ull, a0b = 0ull, a1a = 0ull, a1b = 0ull;
                unsigned long long a2a = 0ull, a2b = 0ull, a3a = 0ull, a3b = 0ull;
                #pragma unroll
                for (int q = 0; q < 8; q++) {
                    ulonglong2 v = *(const ulonglong2*)(xr + off[q]);
                    a0a = fma2(v.x, wp[0][2 * q],     a0a);
                    a0b = fma2(v.y, wp[0][2 * q + 1], a0b);
                    a1a = fma2(v.x, wp[1][2 * q],     a1a);
                    a1b = fma2(v.y, wp[1][2 * q + 1], a1b);
                    a2a = fma2(v.x, wp[2][2 * q],     a2a);
                    a2b = fma2(v.y, wp[2][2 * q + 1], a2b);
                    a3a = fma2(v.x, wp[3][2 * q],     a3a);
                    a3b = fma2(v.y, wp[3][2 * q + 1], a3b);
                }
                F2U s0, s1, s2, s3;
                s0.u = add2(a0a, a0b); s1.u = add2(a1a, a1b);
                s2.u = add2(a2a, a2b); s3.u = add2(a3a, a3b);
                float* pb = ps + (size_t)(b * 32 + td * 4) * PST + ks;
                pb[0 * PST] = s0.f.x + s0.f.y;
                pb[1 * PST] = s1.f.x + s1.f.y;
                pb[2 * PST] = s2.f.x + s2.f.y;
                pb[3 * PST] = s3.f.x + s3.f.y;
            }
        }
        __syncthreads();

        // ---- reduction: outputs 2*tid and 2*tid+1 ----
        float sum0 = 0.f, sum1 = 0.f;
        {
            const float* p0 = ps + (size_t)(2 * tid) * PST;
            const float* p1 = p0 + PST;
            #pragma unroll
            for (int i = 0; i < 32; i++) { sum0 += p0[i]; sum1 += p1[i]; }
        }

        // ---- epilogue: tanh + leak(register) + mask + store ----
        {
            float m = (t < len) ? 1.f : 0.f;
            float2 y;
            y.x = (0.5f * tanhf(uv.x + sum0) + 0.5f * xo.x) * m;
            y.y = (0.5f * tanhf(uv.y + sum1) + 0.5f * xo.y) * m;
            *(float2*)(orow + (size_t)t * DIM) = y;
            xo = y;
        }
        // prefetch next step's u
        {
            int tn = (t + 1 < T_MAX) ? t + 1 : t;
            uv = __ldcg((const float2*)(orow + (size_t)tn * DIM));
        }

        // ---- per-group grid barrier (32 CTAs) ----
        __syncthreads();
        if (tid == 0) {
            unsigned* ctr = ctr_base + t;
            asm volatile("red.release.gpu.global.add.u32 [%0], 1;" :: "l"(ctr) : "memory");
            unsigned v;
            do {
                asm volatile("ld.relaxed.gpu.global.u32 %0, [%1];" : "=r"(v) : "l"(ctr) : "memory");
            } while (v < GRP_CTAS);
            asm volatile("ld.acquire.gpu.global.u32 %0, [%1];" : "=r"(v) : "l"(ctr) : "memory");
        }
        __syncthreads();
    }
}

// ---------------------------------------------------------------------------
extern "C" void kernel_launch(void* const* d_in, const int* in_sizes, int n_in,
                              void* d_out, int out_size) {
    const float* emb  = (const float*)d_in[0];
    const float* win  = (const float*)d_in[1];
    const float* lw   = (const float*)d_in[2];
    const float* bias = (const float*)d_in[3];
    const float* init = (const float*)d_in[4];
    float* out = (float*)d_out;

    zero_kernel<<<8, 256>>>();
    prep_kernel<<<512, 256>>>(emb);

    dim3 g(T_MAX, DIM / 128);
    ugemm_kernel<<<g, 256>>>(emb, win, bias, out);

    int smem = (16 * 1024 + 512 * PST) * (int)sizeof(float);   // ~130 KB
    cudaFuncSetAttribute(rec_kernel, cudaFuncAttributeMaxDynamicSharedMemorySize, smem);
    rec_kernel<<<NCTA, 256, smem>>>(lw, init, out);

    tail_kernel<<<1, 64>>>(out, out_size);
}